// round 1
// baseline (speedup 1.0000x reference)
#include <cuda_runtime.h>
#include <cuda_bf16.h>
#include <cstdint>
#include <cstddef>

// ---------------------------------------------------------------------------
// BitNet FFN: x[8192,2048] -> bitlinear(w1[8192,2048]) -> gelu -> bitlinear(w2)
// Integer-exact formulation: quantized activations/weights are small integers;
// bf16 tensor-core MMA with fp32 accum reproduces the integer sums exactly.
// ---------------------------------------------------------------------------

#define EPSQ 1e-5f

#define TOKENS   8192     // 4 * 2048
#define DMODEL   2048
#define DHIDDEN  8192

// ------------------------- device scratch (no allocs) ----------------------
__device__ float          g_partial[4096];
__device__ float          g_scales[2];                       // s_w1, s_w2 = 1/clip(mean|w|,eps)
__device__ __nv_bfloat16  g_w1q[(size_t)DHIDDEN * DMODEL];   // 32 MB
__device__ __nv_bfloat16  g_w2q[(size_t)DMODEL * DHIDDEN];   // 32 MB
__device__ __nv_bfloat16  g_xq [(size_t)TOKENS * DMODEL];    // 32 MB
__device__ float          g_xscale[TOKENS];
__device__ float          g_c1 [(size_t)TOKENS * DHIDDEN];   // 256 MB raw int sums (fp32)
__device__ __nv_bfloat16  g_hq [(size_t)TOKENS * DHIDDEN];   // 128 MB
__device__ float          g_hscale[TOKENS];

// ------------------------------- helpers -----------------------------------
__device__ __forceinline__ float gelu_exact(float v) {
    return 0.5f * v * (1.0f + erff(v * 0.70710678118654752440f));
}
__device__ __forceinline__ float q_act(float v, float s) {          // int8 quant value
    return fminf(fmaxf(rintf(v * s), -128.0f), 127.0f);
}
__device__ __forceinline__ float q_w(float v, float s) {            // ternary quant value
    return fminf(fmaxf(rintf(v * s), -1.0f), 1.0f);
}
__device__ __forceinline__ uint32_t pack_bf2(float a, float b) {
    __nv_bfloat162 h = __floats2bfloat162_rn(a, b);
    return *reinterpret_cast<uint32_t*>(&h);
}
__device__ __forceinline__ uint32_t smem_u32(const void* p) {
    return (uint32_t)__cvta_generic_to_shared(p);
}
__device__ __forceinline__ void ldm_x4(uint32_t* r, uint32_t addr) {
    asm volatile("ldmatrix.sync.aligned.m8n8.x4.shared.b16 {%0,%1,%2,%3}, [%4];"
                 : "=r"(r[0]), "=r"(r[1]), "=r"(r[2]), "=r"(r[3]) : "r"(addr));
}
__device__ __forceinline__ void ldm_x2(uint32_t* r, uint32_t addr) {
    asm volatile("ldmatrix.sync.aligned.m8n8.x2.shared.b16 {%0,%1}, [%2];"
                 : "=r"(r[0]), "=r"(r[1]) : "r"(addr));
}
__device__ __forceinline__ void mma16816(float* d, const uint32_t* a, const uint32_t* b) {
    asm volatile("mma.sync.aligned.m16n8k16.row.col.f32.bf16.bf16.f32 "
                 "{%0,%1,%2,%3}, {%4,%5,%6,%7}, {%8,%9}, {%0,%1,%2,%3};"
                 : "+f"(d[0]), "+f"(d[1]), "+f"(d[2]), "+f"(d[3])
                 : "r"(a[0]), "r"(a[1]), "r"(a[2]), "r"(a[3]),
                   "r"(b[0]), "r"(b[1]));
}

// ------------------------- K0: |w| partial sums -----------------------------
// blocks 0..2047 -> w1 (contiguous 8192-elem chunks), 2048..4095 -> w2
__global__ void k_wsum(const float* __restrict__ w1, const float* __restrict__ w2) {
    int b = blockIdx.x;
    const float* w = (b < 2048) ? w1 : w2;
    size_t base = (size_t)(b & 2047) * 8192;
    float s = 0.0f;
    #pragma unroll 8
    for (int i = 0; i < 32; i++)
        s += fabsf(w[base + threadIdx.x + i * 256]);
    __shared__ float red[256];
    red[threadIdx.x] = s; __syncthreads();
    for (int o = 128; o > 0; o >>= 1) {
        if (threadIdx.x < o) red[threadIdx.x] += red[threadIdx.x + o];
        __syncthreads();
    }
    if (threadIdx.x == 0) g_partial[b] = red[0];
}

// ------------------------- K0b: finalize scales -----------------------------
__global__ void k_scales() {
    __shared__ float red[256];
    float s = 0.0f;
    for (int i = threadIdx.x; i < 2048; i += 256) s += g_partial[i];
    red[threadIdx.x] = s; __syncthreads();
    for (int o = 128; o > 0; o >>= 1) {
        if (threadIdx.x < o) red[threadIdx.x] += red[threadIdx.x + o];
        __syncthreads();
    }
    float sum1 = red[0];
    __syncthreads();
    s = 0.0f;
    for (int i = threadIdx.x; i < 2048; i += 256) s += g_partial[2048 + i];
    red[threadIdx.x] = s; __syncthreads();
    for (int o = 128; o > 0; o >>= 1) {
        if (threadIdx.x < o) red[threadIdx.x] += red[threadIdx.x + o];
        __syncthreads();
    }
    if (threadIdx.x == 0) {
        float m1 = sum1   * (1.0f / 16777216.0f);
        float m2 = red[0] * (1.0f / 16777216.0f);
        g_scales[0] = 1.0f / fmaxf(m1, EPSQ);
        g_scales[1] = 1.0f / fmaxf(m2, EPSQ);
    }
}

// ------------------------- K1: ternary-quantize weights --------------------
// grid 16384: first 8192 blocks -> w1, rest -> w2. 8 floats/thread.
__global__ void k_wquant(const float* __restrict__ w1, const float* __restrict__ w2) {
    bool second = blockIdx.x >= 8192;
    const float* w = second ? w2 : w1;
    __nv_bfloat16* o = second ? g_w2q : g_w1q;
    float s = g_scales[second ? 1 : 0];
    size_t idx = ((size_t)(blockIdx.x & 8191) * 256 + threadIdx.x) * 8;
    float4 v0 = *reinterpret_cast<const float4*>(w + idx);
    float4 v1 = *reinterpret_cast<const float4*>(w + idx + 4);
    uint4 out;
    out.x = pack_bf2(q_w(v0.x, s), q_w(v0.y, s));
    out.y = pack_bf2(q_w(v0.z, s), q_w(v0.w, s));
    out.z = pack_bf2(q_w(v1.x, s), q_w(v1.y, s));
    out.w = pack_bf2(q_w(v1.z, s), q_w(v1.w, s));
    *reinterpret_cast<uint4*>(o + idx) = out;
}

// ------------------------- K2: per-token int8 quant of x --------------------
__global__ void k_xquant(const float* __restrict__ x) {
    int m = blockIdx.x, tid = threadIdx.x;
    const float4* row = reinterpret_cast<const float4*>(x + (size_t)m * DMODEL);
    float4 v0 = row[tid], v1 = row[tid + 256];
    float amax = fmaxf(fmaxf(fmaxf(fabsf(v0.x), fabsf(v0.y)), fmaxf(fabsf(v0.z), fabsf(v0.w))),
                       fmaxf(fmaxf(fabsf(v1.x), fabsf(v1.y)), fmaxf(fabsf(v1.z), fabsf(v1.w))));
    __shared__ float red[256];
    red[tid] = amax; __syncthreads();
    for (int o = 128; o > 0; o >>= 1) {
        if (tid < o) red[tid] = fmaxf(red[tid], red[tid + o]);
        __syncthreads();
    }
    float scale = 127.0f / fmaxf(red[0], EPSQ);
    uint2 o0, o1;
    o0.x = pack_bf2(q_act(v0.x, scale), q_act(v0.y, scale));
    o0.y = pack_bf2(q_act(v0.z, scale), q_act(v0.w, scale));
    o1.x = pack_bf2(q_act(v1.x, scale), q_act(v1.y, scale));
    o1.y = pack_bf2(q_act(v1.z, scale), q_act(v1.w, scale));
    uint2* orow = reinterpret_cast<uint2*>(g_xq + (size_t)m * DMODEL);
    orow[tid] = o0;
    orow[tid + 256] = o1;
    if (tid == 0) g_xscale[m] = scale;
}

// ------------------------- K4: dequant + gelu + row requant -----------------
__global__ void k_hquant() {
    int m = blockIdx.x, tid = threadIdx.x;
    const float4* crow = reinterpret_cast<const float4*>(g_c1 + (size_t)m * DHIDDEN);
    float f = 1.0f / (g_xscale[m] * g_scales[0]);   // exact dequant of integer sums
    float gv[32];
    float amax = 0.0f;
    #pragma unroll
    for (int j = 0; j < 8; j++) {
        float4 v = crow[tid + j * 256];
        float a = gelu_exact(v.x * f), b = gelu_exact(v.y * f);
        float c = gelu_exact(v.z * f), d = gelu_exact(v.w * f);
        gv[j * 4 + 0] = a; gv[j * 4 + 1] = b; gv[j * 4 + 2] = c; gv[j * 4 + 3] = d;
        amax = fmaxf(amax, fmaxf(fmaxf(fabsf(a), fabsf(b)), fmaxf(fabsf(c), fabsf(d))));
    }
    __shared__ float red[256];
    red[tid] = amax; __syncthreads();
    for (int o = 128; o > 0; o >>= 1) {
        if (tid < o) red[tid] = fmaxf(red[tid], red[tid + o]);
        __syncthreads();
    }
    float scale = 127.0f / fmaxf(red[0], EPSQ);
    uint2* orow = reinterpret_cast<uint2*>(g_hq + (size_t)m * DHIDDEN);
    #pragma unroll
    for (int j = 0; j < 8; j++) {
        uint2 o;
        o.x = pack_bf2(q_act(gv[j * 4 + 0], scale), q_act(gv[j * 4 + 1], scale));
        o.y = pack_bf2(q_act(gv[j * 4 + 2], scale), q_act(gv[j * 4 + 3], scale));
        orow[tid + j * 256] = o;
    }
    if (tid == 0) g_hscale[m] = scale;
}

// ------------------------- GEMM: 128x128 tile, mma.sync bf16 ----------------
// C[m,n] = sum_k A[m,k] * B[n,k]  (both K-major; B acts as col-major operand).
// MODE 0: A=g_xq (K=2048), B=g_w1q, write raw sums to g_c1.
// MODE 1: A=g_hq (K=8192), B=g_w2q, write dequantized fp32 to Cout.
template <int KDIM, int MODE>
__global__ void __launch_bounds__(256, 2) k_gemm(float* __restrict__ Cout) {
    constexpr int KT  = KDIM / 32;
    constexpr int LDS = 40;                    // padded smem row (bf16 elems)

    __shared__ __align__(16) __nv_bfloat16 As[2][128 * LDS];
    __shared__ __align__(16) __nv_bfloat16 Bs[2][128 * LDS];

    const __nv_bfloat16* __restrict__ A = (MODE == 0) ? g_xq  : g_hq;
    const __nv_bfloat16* __restrict__ B = (MODE == 0) ? g_w1q : g_w2q;

    const int tid    = threadIdx.x;
    const int mblock = blockIdx.y * 128;
    const int nblock = blockIdx.x * 128;
    const int warp = tid >> 5, lane = tid & 31;
    const int wm = (warp >> 1) * 32;           // 4 warps along M
    const int wn = (warp & 1) * 64;            // 2 warps along N

    // per-lane ldmatrix row/col components
    const int aRow = wm + (lane & 15);
    const int aCol = (lane >> 4) * 8;
    const int bRow = wn + (lane & 7);
    const int bCol = ((lane >> 3) & 1) * 8;

    const uint32_t asb[2] = { smem_u32(&As[0][0]), smem_u32(&As[1][0]) };
    const uint32_t bsb[2] = { smem_u32(&Bs[0][0]), smem_u32(&Bs[1][0]) };

    float acc[2][8][4];
    #pragma unroll
    for (int i = 0; i < 2; i++)
        #pragma unroll
        for (int j = 0; j < 8; j++)
            #pragma unroll
            for (int k = 0; k < 4; k++) acc[i][j][k] = 0.0f;

    uint4 stA[2], stB[2];
    // per-thread load geometry (512 16B chunks per tile side, 2 per thread)
    const int c0 = tid, c1 = tid + 256;
    const int rA0 = c0 >> 2, kA0 = (c0 & 3) * 8;
    const int rA1 = c1 >> 2, kA1 = (c1 & 3) * 8;

    // prologue: tile 0
    stA[0] = *reinterpret_cast<const uint4*>(A + (size_t)(mblock + rA0) * KDIM + kA0);
    stA[1] = *reinterpret_cast<const uint4*>(A + (size_t)(mblock + rA1) * KDIM + kA1);
    stB[0] = *reinterpret_cast<const uint4*>(B + (size_t)(nblock + rA0) * KDIM + kA0);
    stB[1] = *reinterpret_cast<const uint4*>(B + (size_t)(nblock + rA1) * KDIM + kA1);
    *reinterpret_cast<uint4*>(&As[0][rA0 * LDS + kA0]) = stA[0];
    *reinterpret_cast<uint4*>(&As[0][rA1 * LDS + kA1]) = stA[1];
    *reinterpret_cast<uint4*>(&Bs[0][rA0 * LDS + kA0]) = stB[0];
    *reinterpret_cast<uint4*>(&Bs[0][rA1 * LDS + kA1]) = stB[1];
    __syncthreads();

    #pragma unroll 2
    for (int kt = 0; kt < KT; kt++) {
        const int buf = kt & 1;
        if (kt + 1 < KT) {
            const int koff = (kt + 1) * 32;
            stA[0] = *reinterpret_cast<const uint4*>(A + (size_t)(mblock + rA0) * KDIM + koff + kA0);
            stA[1] = *reinterpret_cast<const uint4*>(A + (size_t)(mblock + rA1) * KDIM + koff + kA1);
            stB[0] = *reinterpret_cast<const uint4*>(B + (size_t)(nblock + rA0) * KDIM + koff + kA0);
            stB[1] = *reinterpret_cast<const uint4*>(B + (size_t)(nblock + rA1) * KDIM + koff + kA1);
        }

        #pragma unroll
        for (int kk = 0; kk < 2; kk++) {
            uint32_t af[2][4], bf[8][2];
            #pragma unroll
            for (int mt = 0; mt < 2; mt++)
                ldm_x4(af[mt], asb[buf] + (uint32_t)(((aRow + mt * 16) * LDS + kk * 16 + aCol) * 2));
            #pragma unroll
            for (int nt = 0; nt < 8; nt++)
                ldm_x2(bf[nt], bsb[buf] + (uint32_t)(((bRow + nt * 8) * LDS + kk * 16 + bCol) * 2));
            #pragma unroll
            for (int mt = 0; mt < 2; mt++)
                #pragma unroll
                for (int nt = 0; nt < 8; nt++)
                    mma16816(acc[mt][nt], af[mt], bf[nt]);
        }

        if (kt + 1 < KT) {
            const int nb = (kt + 1) & 1;
            *reinterpret_cast<uint4*>(&As[nb][rA0 * LDS + kA0]) = stA[0];
            *reinterpret_cast<uint4*>(&As[nb][rA1 * LDS + kA1]) = stA[1];
            *reinterpret_cast<uint4*>(&Bs[nb][rA0 * LDS + kA0]) = stB[0];
            *reinterpret_cast<uint4*>(&Bs[nb][rA1 * LDS + kA1]) = stB[1];
        }
        __syncthreads();
    }

    // ---- epilogue ----
    const int gq = lane >> 2;
    const int tc = (lane & 3) * 2;
    #pragma unroll
    for (int mt = 0; mt < 2; mt++) {
        const int m0 = mblock + wm + mt * 16 + gq;
        float inv0 = 1.0f, inv1 = 1.0f;
        if (MODE == 1) {
            inv0 = 1.0f / (g_hscale[m0]     * g_scales[1]);
            inv1 = 1.0f / (g_hscale[m0 + 8] * g_scales[1]);
        }
        #pragma unroll
        for (int nt = 0; nt < 8; nt++) {
            const int n0 = nblock + wn + nt * 8 + tc;
            if (MODE == 0) {
                float2 v0 = make_float2(acc[mt][nt][0], acc[mt][nt][1]);
                float2 v1 = make_float2(acc[mt][nt][2], acc[mt][nt][3]);
                *reinterpret_cast<float2*>(&g_c1[(size_t)m0 * DHIDDEN + n0])       = v0;
                *reinterpret_cast<float2*>(&g_c1[(size_t)(m0 + 8) * DHIDDEN + n0]) = v1;
            } else {
                float2 v0 = make_float2(acc[mt][nt][0] * inv0, acc[mt][nt][1] * inv0);
                float2 v1 = make_float2(acc[mt][nt][2] * inv1, acc[mt][nt][3] * inv1);
                *reinterpret_cast<float2*>(&Cout[(size_t)m0 * DMODEL + n0])       = v0;
                *reinterpret_cast<float2*>(&Cout[(size_t)(m0 + 8) * DMODEL + n0]) = v1;
            }
        }
    }
}

// ------------------------------- launch -------------------------------------
extern "C" void kernel_launch(void* const* d_in, const int* in_sizes, int n_in,
                              void* d_out, int out_size) {
    const float* x  = (const float*)d_in[0];
    const float* w1 = (const float*)d_in[1];
    const float* w2 = (const float*)d_in[2];
    float* out = (float*)d_out;

    k_wsum  <<<4096, 256>>>(w1, w2);
    k_scales<<<1,    256>>>();
    k_wquant<<<16384, 256>>>(w1, w2);
    k_xquant<<<TOKENS, 256>>>(x);

    k_gemm<DMODEL, 0><<<dim3(DHIDDEN / 128, TOKENS / 128), 256>>>(nullptr);
    k_hquant<<<TOKENS, 256>>>();
    k_gemm<DHIDDEN, 1><<<dim3(DMODEL / 128, TOKENS / 128), 256>>>(out);
}